// round 2
// baseline (speedup 1.0000x reference)
#include <cuda_runtime.h>
#include <cstdint>
#include <cstddef>

#define NG 128      // graphs
#define NN 256      // nodes per graph
#define DF 128      // feature dim
#define KB 16       // histogram bins
#define KC 32       // k-chunk for gram tiles
#define LDT 132     // smem tile row stride (floats), mult of 4 for LDS.128

// ---------------- scratch (device globals: allocation-free rule) ----------------
__device__ float g_D[(size_t)2 * NG * NN * NN];   // 64 MB distance scratch
__device__ float g_sq[2 * NG * NN];               // per-node squared norms
__device__ float g_dpart[2 * NG * 4];             // per-tile-block D sums
__device__ float g_hpart[2 * NG * 4 * KB];        // per-block partial histograms
__device__ float g_sig[2 * NG * KB];              // normalized signatures
__device__ float g_zinv[2 * NG];                  // 1/(||z||+eps)
__device__ float g_rowloss[2 * NG];               // per-row ntxent loss

// =======================================================================
// Kernel 0: per-node squared norms. grid = 256 (gs), 256 threads (row).
// =======================================================================
__global__ __launch_bounds__(256) void k_sq(const float* __restrict__ H1,
                                            const float* __restrict__ H2) {
    int gs = blockIdx.x;
    const float* H = (gs < NG) ? (H1 + (size_t)gs * NN * DF)
                               : (H2 + (size_t)(gs - NG) * NN * DF);
    int r = threadIdx.x;
    const float* row = H + (size_t)r * DF;
    float s = 0.f;
    #pragma unroll
    for (int k = 0; k < DF; k += 4) {
        float4 v = *(const float4*)(row + k);
        s += v.x * v.x + v.y * v.y + v.z * v.z + v.w * v.w;
    }
    g_sq[gs * NN + r] = s;
}

// =======================================================================
// Kernel 1: Gram -> pairwise distances.
// grid = 1024: (gs: 0..255) x (2x2 tiles of 128x128). 256 threads.
// Each thread: 16 rows x 4 cols register tile. Static smem ~35 KB.
// =======================================================================
__global__ __launch_bounds__(256) void k_gram(const float* __restrict__ H1,
                                              const float* __restrict__ H2) {
    int b = blockIdx.x;          // 0..1023
    int gs = b >> 2;             // 0..255
    int ti = (b >> 1) & 1;       // row tile
    int tj = b & 1;              // col tile
    const float* H = (gs < NG) ? (H1 + (size_t)gs * NN * DF)
                               : (H2 + (size_t)(gs - NG) * NN * DF);

    __shared__ float As[KC][LDT];
    __shared__ float Bs[KC][LDT];
    __shared__ float sqs[NN];
    __shared__ float wsum[8];

    int tid = threadIdx.x;
    sqs[tid] = g_sq[gs * NN + tid];

    const float* Arow = H + (size_t)(ti * 128) * DF;
    const float* Brow = H + (size_t)(tj * 128) * DF;

    int tx = tid & 31, ty = tid >> 5;
    int rbase = ty * 16;         // 16 rows per thread
    int cbase = tx * 4;          // 4 consecutive cols per thread

    float acc[16][4];
    #pragma unroll
    for (int i = 0; i < 16; i++)
        #pragma unroll
        for (int j = 0; j < 4; j++) acc[i][j] = 0.f;

    #pragma unroll 1
    for (int k0 = 0; k0 < DF; k0 += KC) {
        __syncthreads();
        // load 128 rows x KC k (transposed to k-major); coalesced global reads
        #pragma unroll
        for (int e = tid; e < 128 * KC; e += 256) {
            int r = e >> 5;            // KC==32 per row
            int kk = e & 31;
            As[kk][r] = Arow[r * DF + k0 + kk];
            Bs[kk][r] = Brow[r * DF + k0 + kk];
        }
        __syncthreads();

        #pragma unroll
        for (int k = 0; k < KC; k++) {
            float4 a0 = *(const float4*)&As[k][rbase];       // broadcast
            float4 a1 = *(const float4*)&As[k][rbase + 4];
            float4 a2 = *(const float4*)&As[k][rbase + 8];
            float4 a3 = *(const float4*)&As[k][rbase + 12];
            float4 bb = *(const float4*)&Bs[k][cbase];       // lane-consecutive
            float a[16] = {a0.x, a0.y, a0.z, a0.w, a1.x, a1.y, a1.z, a1.w,
                           a2.x, a2.y, a2.z, a2.w, a3.x, a3.y, a3.z, a3.w};
            #pragma unroll
            for (int i = 0; i < 16; i++) {
                acc[i][0] = fmaf(a[i], bb.x, acc[i][0]);
                acc[i][1] = fmaf(a[i], bb.y, acc[i][1]);
                acc[i][2] = fmaf(a[i], bb.z, acc[i][2]);
                acc[i][3] = fmaf(a[i], bb.w, acc[i][3]);
            }
        }
    }

    // epilogue: distances, store, local sum
    float lsum = 0.f;
    float* Dout = g_D + (size_t)gs * NN * NN + (size_t)(ti * 128) * NN + tj * 128;
    float sqc0 = sqs[tj * 128 + cbase + 0];
    float sqc1 = sqs[tj * 128 + cbase + 1];
    float sqc2 = sqs[tj * 128 + cbase + 2];
    float sqc3 = sqs[tj * 128 + cbase + 3];
    #pragma unroll
    for (int i = 0; i < 16; i++) {
        int r = rbase + i;
        float sqr = sqs[ti * 128 + r];
        float4 o;
        o.x = sqrtf(fmaxf(sqr + sqc0 - 2.f * acc[i][0], 0.f) + 1e-12f);
        o.y = sqrtf(fmaxf(sqr + sqc1 - 2.f * acc[i][1], 0.f) + 1e-12f);
        o.z = sqrtf(fmaxf(sqr + sqc2 - 2.f * acc[i][2], 0.f) + 1e-12f);
        o.w = sqrtf(fmaxf(sqr + sqc3 - 2.f * acc[i][3], 0.f) + 1e-12f);
        lsum += o.x + o.y + o.z + o.w;
        *(float4*)&Dout[(size_t)r * NN + cbase] = o;
    }

    // deterministic block reduction of lsum
    #pragma unroll
    for (int o = 16; o > 0; o >>= 1) lsum += __shfl_down_sync(0xffffffffu, lsum, o);
    if (tx == 0) wsum[ty] = lsum;
    __syncthreads();
    if (tid == 0) {
        float s = 0.f;
        #pragma unroll
        for (int w = 0; w < 8; w++) s += wsum[w];
        g_dpart[b] = s;
    }
}

// =======================================================================
// Kernel 2: soft histogram partials. grid = 1024 (gs x quarter).
// w_k = exp(-0.5*((Dn - 0.2k)/sigma)^2) = exp2(-(Dn*A - k*B)^2)
// =======================================================================
__global__ __launch_bounds__(256) void k_hist() {
    int b = blockIdx.x;            // 0..1023
    int gs = b >> 2, q = b & 3;
    float mu = (g_dpart[gs * 4 + 0] + g_dpart[gs * 4 + 1] +
                g_dpart[gs * 4 + 2] + g_dpart[gs * 4 + 3]) * (1.f / 65536.f);
    float inv = 1.f / (mu + 1e-8f);
    const float A = 4.52971643f;   // sqrt(0.5*log2(e)) / sigma
    const float B = 0.90594329f;   // 0.2 * A

    float h[KB];
    #pragma unroll
    for (int k = 0; k < KB; k++) h[k] = 0.f;

    const float4* Dp = (const float4*)(g_D + (size_t)gs * NN * NN + (size_t)q * 16384);
    float iA = inv * A;
    #pragma unroll 1
    for (int idx = threadIdx.x; idx < 4096; idx += 256) {
        float4 d4 = Dp[idx];
        float xa0 = d4.x * iA, xa1 = d4.y * iA, xa2 = d4.z * iA, xa3 = d4.w * iA;
        #pragma unroll
        for (int k = 0; k < KB; k++) {
            float c = B * (float)k;
            float p0 = xa0 - c, p1 = xa1 - c, p2 = xa2 - c, p3 = xa3 - c;
            float w0, w1, w2, w3;
            asm("ex2.approx.ftz.f32 %0, %1;" : "=f"(w0) : "f"(-p0 * p0));
            asm("ex2.approx.ftz.f32 %0, %1;" : "=f"(w1) : "f"(-p1 * p1));
            asm("ex2.approx.ftz.f32 %0, %1;" : "=f"(w2) : "f"(-p2 * p2));
            asm("ex2.approx.ftz.f32 %0, %1;" : "=f"(w3) : "f"(-p3 * p3));
            h[k] += (w0 + w1) + (w2 + w3);
        }
    }

    __shared__ float sh[8][KB];
    int ty = threadIdx.x >> 5, tx = threadIdx.x & 31;
    #pragma unroll
    for (int k = 0; k < KB; k++) {
        float v = h[k];
        #pragma unroll
        for (int o = 16; o > 0; o >>= 1) v += __shfl_down_sync(0xffffffffu, v, o);
        if (tx == 0) sh[ty][k] = v;
    }
    __syncthreads();
    if (threadIdx.x < KB) {
        float s = 0.f;
        #pragma unroll
        for (int w = 0; w < 8; w++) s += sh[w][threadIdx.x];
        g_hpart[b * KB + threadIdx.x] = s;
    }
}

// =======================================================================
// Kernel 3: combine partials -> normalized signatures. 1 block, 256 threads.
// =======================================================================
__global__ void k_sig() {
    int gs = threadIdx.x;          // 0..255
    float h[KB];
    float tot = 0.f;
    #pragma unroll
    for (int k = 0; k < KB; k++) {
        float s = g_hpart[(gs * 4 + 0) * KB + k] + g_hpart[(gs * 4 + 1) * KB + k] +
                  g_hpart[(gs * 4 + 2) * KB + k] + g_hpart[(gs * 4 + 3) * KB + k];
        h[k] = s;
        tot += s;
    }
    float inv = 1.f / (tot + 1e-8f);
    #pragma unroll
    for (int k = 0; k < KB; k++) g_sig[gs * KB + k] = h[k] * inv;
}

// =======================================================================
// Kernel 4: z inverse norms. 1 block, 256 threads.
// =======================================================================
__global__ void k_znorm(const float* __restrict__ z1, const float* __restrict__ z2) {
    int i = threadIdx.x;
    const float* z = (i < NG) ? (z1 + (size_t)i * DF) : (z2 + (size_t)(i - NG) * DF);
    float s = 0.f;
    #pragma unroll
    for (int k = 0; k < DF; k += 4) {
        float4 v = *(const float4*)(z + k);
        s += v.x * v.x + v.y * v.y + v.z * v.z + v.w * v.w;
    }
    g_zinv[i] = 1.f / (sqrtf(s) + 1e-8f);
}

// =======================================================================
// Kernel 5: NT-Xent per-row loss. grid = 256 rows, 256 threads.
// =======================================================================
__global__ __launch_bounds__(256) void k_ntx(const float* __restrict__ z1,
                                             const float* __restrict__ z2) {
    int i = blockIdx.x;
    int tid = threadIdx.x;
    __shared__ float zi[DF];
    __shared__ float red[8];
    __shared__ float s_lab;

    const float* zrow_i = (i < NG) ? (z1 + (size_t)i * DF) : (z2 + (size_t)(i - NG) * DF);
    if (tid < DF / 4) ((float4*)zi)[tid] = ((const float4*)zrow_i)[tid];
    __syncthreads();

    int j = tid;
    const float* zrow_j = (j < NG) ? (z1 + (size_t)j * DF) : (z2 + (size_t)(j - NG) * DF);
    float dot = 0.f;
    #pragma unroll
    for (int k = 0; k < DF; k += 4) {
        float4 v = *(const float4*)(zrow_j + k);
        dot += zi[k] * v.x + zi[k + 1] * v.y + zi[k + 2] * v.z + zi[k + 3] * v.w;
    }
    float sim = dot * g_zinv[i] * g_zinv[j] * 2.0f;   // 1/TEMP = 2
    if (j == i) sim = -1e9f;

    int label = (i < NG) ? (i + NG) : (i - NG);
    if (j == label) s_lab = sim;

    int ty = tid >> 5, tx = tid & 31;
    float mx = sim;
    #pragma unroll
    for (int o = 16; o > 0; o >>= 1) mx = fmaxf(mx, __shfl_xor_sync(0xffffffffu, mx, o));
    if (tx == 0) red[ty] = mx;
    __syncthreads();
    float bm = red[0];
    #pragma unroll
    for (int w = 1; w < 8; w++) bm = fmaxf(bm, red[w]);

    float e = __expf(sim - bm);
    #pragma unroll
    for (int o = 16; o > 0; o >>= 1) e += __shfl_xor_sync(0xffffffffu, e, o);
    __syncthreads();               // WAR on red
    if (tx == 0) red[ty] = e;
    __syncthreads();
    if (tid == 0) {
        float s = 0.f;
        #pragma unroll
        for (int w = 0; w < 8; w++) s += red[w];
        float lse = bm + logf(s);
        g_rowloss[i] = lse - s_lab;
    }
}

// =======================================================================
// Kernel 6: final reduction. 1 block, 256 threads.
// =======================================================================
__global__ void k_final(float* __restrict__ out) {
    int tid = threadIdx.x;
    __shared__ float red[8];

    float c = g_rowloss[tid] * (1.f / 256.f);    // ntxent contribution
    if (tid < NG) {                               // topo contribution
        float t = 0.f;
        #pragma unroll
        for (int k = 0; k < KB; k++) {
            float d = g_sig[tid * KB + k] - g_sig[(NG + tid) * KB + k];
            t += d * d;
        }
        c += t * (1.f / (float)(KB * NG));
    }

    int ty = tid >> 5, tx = tid & 31;
    #pragma unroll
    for (int o = 16; o > 0; o >>= 1) c += __shfl_down_sync(0xffffffffu, c, o);
    if (tx == 0) red[ty] = c;
    __syncthreads();
    if (tid == 0) {
        float s = 0.f;
        #pragma unroll
        for (int w = 0; w < 8; w++) s += red[w];
        out[0] = 0.1f * s;    // LAMBDA
    }
}

// =======================================================================
extern "C" void kernel_launch(void* const* d_in, const int* in_sizes, int n_in,
                              void* d_out, int out_size) {
    const float* H1 = (const float*)d_in[0];
    const float* H2 = (const float*)d_in[2];
    const float* z1 = (const float*)d_in[4];
    const float* z2 = (const float*)d_in[5];
    float* out = (float*)d_out;

    k_sq<<<256, 256>>>(H1, H2);
    k_gram<<<1024, 256>>>(H1, H2);
    k_hist<<<1024, 256>>>();
    k_sig<<<1, 256>>>();
    k_znorm<<<1, 256>>>(z1, z2);
    k_ntx<<<256, 256>>>(z1, z2);
    k_final<<<1, 256>>>(out);
}

// round 4
// speedup vs baseline: 2.1953x; 2.1953x over previous
#include <cuda_runtime.h>
#include <cuda_bf16.h>
#include <cuda_fp16.h>
#include <mma.h>
#include <cstdint>
#include <cstddef>

using namespace nvcuda;

#define NG 128      // graphs
#define NN 256      // nodes per graph
#define DF 128      // feature dim
#define KB 16       // histogram bins
#define KC 64       // k-chunk for gram tiles
#define LDA 72      // bf16 smem row stride (halves): 144B rows, ldmatrix conflict-free
#define LDC 132     // f32 epilogue smem row stride

// Gaussian window constants: w = exp2(-(Dn*A - k*B)^2)
//   A = sqrt(0.5*log2(e))/sigma, sigma = 3/16;  B = 0.2*A
#define GA 4.52971643f
#define GB 0.90594329f

// ---------------- scratch (device globals: allocation-free rule) ----------------
__device__ __half g_Dh[(size_t)2 * NG * 3 * 128 * 128];  // 3 tiles/graph-set, fp16 (25MB)
__device__ float g_sq[2 * NG * NN];     // per-node squared norms
__device__ float g_dpart[2 * NG * 3];   // per-tile D sums
__device__ float g_hpart[2 * NG * 4 * KB];
__device__ float g_sig[2 * NG * KB];
__device__ float g_zinv[2 * NG];
__device__ float g_rowloss[2 * NG];

// =======================================================================
// Kernel 0: per-node squared norms (blocks 0..255) + z inv-norms (block 256).
// =======================================================================
__global__ __launch_bounds__(256) void k_sq(const float* __restrict__ H1,
                                            const float* __restrict__ H2,
                                            const float* __restrict__ z1,
                                            const float* __restrict__ z2) {
    int gs = blockIdx.x;
    int r = threadIdx.x;
    if (gs < 2 * NG) {
        const float* H = (gs < NG) ? (H1 + (size_t)gs * NN * DF)
                                   : (H2 + (size_t)(gs - NG) * NN * DF);
        const float* row = H + (size_t)r * DF;
        float s = 0.f;
        #pragma unroll
        for (int k = 0; k < DF; k += 4) {
            float4 v = *(const float4*)(row + k);
            s += v.x * v.x + v.y * v.y + v.z * v.z + v.w * v.w;
        }
        g_sq[gs * NN + r] = s;
    } else {
        const float* z = (r < NG) ? (z1 + (size_t)r * DF) : (z2 + (size_t)(r - NG) * DF);
        float s = 0.f;
        #pragma unroll
        for (int k = 0; k < DF; k += 4) {
            float4 v = *(const float4*)(z + k);
            s += v.x * v.x + v.y * v.y + v.z * v.z + v.w * v.w;
        }
        g_zinv[r] = 1.f / (sqrtf(s) + 1e-8f);
    }
}

// =======================================================================
// Kernel 1: bf16 tensor-core gram -> fp16 distances, 3 tiles per (graph,set).
// grid = 768 (gs * {(0,0),(1,0),(1,1)}), 256 threads (8 warps, 2x4 warp grid,
// each warp a 64x32 subtile via 4x2 wmma 16x16x16 bf16 fragments).
// =======================================================================
__global__ __launch_bounds__(256) void k_gram(const float* __restrict__ H1,
                                              const float* __restrict__ H2) {
    int b = blockIdx.x;
    int gs = b / 3;
    int t = b - gs * 3;
    int ti = (t == 0) ? 0 : 1;
    int tj = (t == 2) ? 1 : 0;
    const float* H = (gs < NG) ? (H1 + (size_t)gs * NN * DF)
                               : (H2 + (size_t)(gs - NG) * NN * DF);
    const float* Arow = H + (size_t)(ti * 128) * DF;
    const float* Brow = H + (size_t)(tj * 128) * DF;

    __shared__ __align__(128) unsigned char smbuf[36864];
    __nv_bfloat16* As = (__nv_bfloat16*)smbuf;
    __nv_bfloat16* Bs = As + 128 * LDA;
    float* Cs = (float*)smbuf;               // reused after MMA (64x132 f32)
    __shared__ float sqs[NN];
    __shared__ float wsum[8];

    int tid = threadIdx.x;
    sqs[tid] = g_sq[gs * NN + tid];

    int w = tid >> 5;
    int wr = w >> 2, wc = w & 3;             // warp row(0..1) x col(0..3)

    wmma::fragment<wmma::accumulator, 16, 16, 16, float> c[4][2];
    #pragma unroll
    for (int i = 0; i < 4; i++)
        #pragma unroll
        for (int j = 0; j < 2; j++) wmma::fill_fragment(c[i][j], 0.f);

    #pragma unroll 1
    for (int k0 = 0; k0 < DF; k0 += KC) {
        __syncthreads();
        #pragma unroll
        for (int it = 0; it < 8; it++) {
            int e = tid + it * 256;
            int row = e >> 4, k4 = e & 15;   // 16 float4 per KC=64 row chunk
            float4 va = *(const float4*)(Arow + row * DF + k0 + k4 * 4);
            float4 vb = *(const float4*)(Brow + row * DF + k0 + k4 * 4);
            __nv_bfloat162* pa = (__nv_bfloat162*)(As + row * LDA + k4 * 4);
            pa[0] = __floats2bfloat162_rn(va.x, va.y);
            pa[1] = __floats2bfloat162_rn(va.z, va.w);
            __nv_bfloat162* pb = (__nv_bfloat162*)(Bs + row * LDA + k4 * 4);
            pb[0] = __floats2bfloat162_rn(vb.x, vb.y);
            pb[1] = __floats2bfloat162_rn(vb.z, vb.w);
        }
        __syncthreads();

        #pragma unroll
        for (int ks = 0; ks < KC / 16; ks++) {
            wmma::fragment<wmma::matrix_a, 16, 16, 16, __nv_bfloat16, wmma::row_major> af[4];
            wmma::fragment<wmma::matrix_b, 16, 16, 16, __nv_bfloat16, wmma::col_major> bf[2];
            #pragma unroll
            for (int i = 0; i < 4; i++)
                wmma::load_matrix_sync(af[i], As + (wr * 64 + i * 16) * LDA + ks * 16, LDA);
            #pragma unroll
            for (int j = 0; j < 2; j++)
                wmma::load_matrix_sync(bf[j], Bs + (wc * 32 + j * 16) * LDA + ks * 16, LDA);
            #pragma unroll
            for (int i = 0; i < 4; i++)
                #pragma unroll
                for (int j = 0; j < 2; j++)
                    wmma::mma_sync(c[i][j], af[i], bf[j], c[i][j]);
        }
    }

    // epilogue in two 64-row passes through the reused smem
    float lsum = 0.f;
    __half* Dout = g_Dh + (size_t)b * 16384;
    #pragma unroll 1
    for (int h = 0; h < 2; h++) {
        __syncthreads();
        if (wr == h) {
            #pragma unroll
            for (int i = 0; i < 4; i++)
                #pragma unroll
                for (int j = 0; j < 2; j++)
                    wmma::store_matrix_sync(Cs + i * 16 * LDC + wc * 32 + j * 16,
                                            c[i][j], LDC, wmma::mem_row_major);
        }
        __syncthreads();
        #pragma unroll
        for (int it = 0; it < 32; it++) {
            int e = tid + it * 256;
            int lr = e >> 7, cc = e & 127;
            float d2 = sqs[ti * 128 + h * 64 + lr] + sqs[tj * 128 + cc]
                     - 2.f * Cs[lr * LDC + cc];
            float d;
            asm("sqrt.approx.f32 %0, %1;" : "=f"(d) : "f"(fmaxf(d2, 0.f) + 1e-12f));
            lsum += d;
            Dout[(h * 64 + lr) * 128 + cc] = __float2half_rn(d);
        }
    }

    #pragma unroll
    for (int o = 16; o > 0; o >>= 1) lsum += __shfl_down_sync(0xffffffffu, lsum, o);
    int tx = tid & 31;
    if (tx == 0) wsum[w] = lsum;
    __syncthreads();
    if (tid == 0) {
        float s = 0.f;
        #pragma unroll
        for (int ww = 0; ww < 8; ww++) s += wsum[ww];
        g_dpart[b] = s;
    }
}

// =======================================================================
// Kernel 2: soft-histogram partials with fp16x2 EX2.
// grid = 1024 = 256 gs x {offdiag half0, offdiag half1, tri(0,0), tri(1,1)}.
// Triangle partial = sum_{i<=j} w - 0.5*sum_diag w (global x2 cancels in norm).
// =======================================================================
__device__ __forceinline__ int tri_off(int e) {
    int p = e / 129;             // row-pair index (rows p and 127-p): 129 elems
    int i = e - p * 129;
    int r, c;
    if (i < 128 - p) { r = p; c = p + i; }
    else             { r = 127 - p; c = i - 1; }
    return r * 128 + c;
}

__global__ __launch_bounds__(256) void k_hist() {
    int b = blockIdx.x;
    int gs = b >> 2, sb = b & 3;
    float mu = (g_dpart[gs * 3 + 0] + 2.f * g_dpart[gs * 3 + 1] + g_dpart[gs * 3 + 2])
               * (1.f / 65536.f);
    float iA = (1.f / (mu + 1e-8f)) * GA;
    __half2 iA2 = __float2half2_rn(iA);
    __half2 ck2[KB];
    #pragma unroll
    for (int k = 0; k < KB; k++) ck2[k] = __float2half2_rn(GB * (float)k);

    float hx[KB], hy[KB];
    #pragma unroll
    for (int k = 0; k < KB; k++) { hx[k] = 0.f; hy[k] = 0.f; }

    if (sb < 2) {
        const __half2* Dp = (const __half2*)(g_Dh + ((size_t)gs * 3 + 1) * 16384
                                             + (size_t)sb * 8192);
        #pragma unroll 1
        for (int idx = threadIdx.x; idx < 4096; idx += 256) {
            __half2 dv = Dp[idx];
            __half2 xa = __hmul2(dv, iA2);
            #pragma unroll
            for (int k = 0; k < KB; k++) {
                __half2 p  = __hsub2(xa, ck2[k]);
                __half2 np = __hsub2(ck2[k], xa);
                __half2 m  = __hmul2(p, np);            // -(xa-ck)^2
                unsigned mu_, wu;
                mu_ = *(unsigned*)&m;
                asm("ex2.approx.f16x2 %0, %1;" : "=r"(wu) : "r"(mu_));
                __half2 wv = *(__half2*)&wu;
                float2 wf = __half22float2(wv);
                hx[k] += wf.x; hy[k] += wf.y;
            }
        }
    } else {
        const __half* Dp = g_Dh + ((size_t)gs * 3 + (sb == 2 ? 0 : 2)) * 16384;
        #pragma unroll 1
        for (int idx = threadIdx.x; idx < 4128; idx += 256) {
            int e0 = idx * 2;
            __half d0 = Dp[tri_off(e0)];
            __half d1 = Dp[tri_off(e0 + 1)];
            __half2 dv = __halves2half2(d0, d1);
            __half2 xa = __hmul2(dv, iA2);
            #pragma unroll
            for (int k = 0; k < KB; k++) {
                __half2 p  = __hsub2(xa, ck2[k]);
                __half2 np = __hsub2(ck2[k], xa);
                __half2 m  = __hmul2(p, np);
                unsigned mu_, wu;
                mu_ = *(unsigned*)&m;
                asm("ex2.approx.f16x2 %0, %1;" : "=r"(wu) : "r"(mu_));
                __half2 wv = *(__half2*)&wu;
                float2 wf = __half22float2(wv);
                hx[k] += wf.x; hy[k] += wf.y;
            }
        }
        // diagonal correction: weight -0.5 (triangle holds i==j once, wants 0.5 rel.)
        if (threadIdx.x < 128) {
            float d = __half2float(Dp[threadIdx.x * 128 + threadIdx.x]);
            float xa = d * iA;
            #pragma unroll
            for (int k = 0; k < KB; k++) {
                float pp = xa - GB * (float)k;
                float wv;
                asm("ex2.approx.ftz.f32 %0, %1;" : "=f"(wv) : "f"(-pp * pp));
                hx[k] -= 0.5f * wv;
            }
        }
    }

    __shared__ float sh[8][KB];
    int ty = threadIdx.x >> 5, tx = threadIdx.x & 31;
    #pragma unroll
    for (int k = 0; k < KB; k++) {
        float v = hx[k] + hy[k];
        #pragma unroll
        for (int o = 16; o > 0; o >>= 1) v += __shfl_down_sync(0xffffffffu, v, o);
        if (tx == 0) sh[ty][k] = v;
    }
    __syncthreads();
    if (threadIdx.x < KB) {
        float s = 0.f;
        #pragma unroll
        for (int w = 0; w < 8; w++) s += sh[w][threadIdx.x];
        g_hpart[b * KB + threadIdx.x] = s;
    }
}

// =======================================================================
// Kernel 3: combine partials -> normalized signatures. grid=16, 256 thr.
// thread = (gs_local, k); 16-lane shfl groups for the normalizer.
// =======================================================================
__global__ void k_sig() {
    int tid = threadIdx.x;
    int gsl = tid >> 4, k = tid & 15;
    int gs = blockIdx.x * 16 + gsl;
    float h = g_hpart[(gs * 4 + 0) * KB + k] + g_hpart[(gs * 4 + 1) * KB + k]
            + g_hpart[(gs * 4 + 2) * KB + k] + g_hpart[(gs * 4 + 3) * KB + k];
    float tot = h;
    #pragma unroll
    for (int o = 8; o > 0; o >>= 1) tot += __shfl_xor_sync(0xffffffffu, tot, o);
    g_sig[gs * KB + k] = h / (tot + 1e-8f);
}

// =======================================================================
// Kernel 4: NT-Xent per-row loss. grid = 256 rows, 256 threads.
// =======================================================================
__global__ __launch_bounds__(256) void k_ntx(const float* __restrict__ z1,
                                             const float* __restrict__ z2) {
    int i = blockIdx.x;
    int tid = threadIdx.x;
    __shared__ float zi[DF];
    __shared__ float red[8];
    __shared__ float s_lab;

    const float* zrow_i = (i < NG) ? (z1 + (size_t)i * DF) : (z2 + (size_t)(i - NG) * DF);
    if (tid < DF / 4) ((float4*)zi)[tid] = ((const float4*)zrow_i)[tid];
    __syncthreads();

    int j = tid;
    const float* zrow_j = (j < NG) ? (z1 + (size_t)j * DF) : (z2 + (size_t)(j - NG) * DF);
    float dot = 0.f;
    #pragma unroll
    for (int k = 0; k < DF; k += 4) {
        float4 v = *(const float4*)(zrow_j + k);
        dot += zi[k] * v.x + zi[k + 1] * v.y + zi[k + 2] * v.z + zi[k + 3] * v.w;
    }
    float sim = dot * g_zinv[i] * g_zinv[j] * 2.0f;   // 1/TEMP = 2
    if (j == i) sim = -1e9f;

    int label = (i < NG) ? (i + NG) : (i - NG);
    if (j == label) s_lab = sim;

    int ty = tid >> 5, tx = tid & 31;
    float mx = sim;
    #pragma unroll
    for (int o = 16; o > 0; o >>= 1) mx = fmaxf(mx, __shfl_xor_sync(0xffffffffu, mx, o));
    if (tx == 0) red[ty] = mx;
    __syncthreads();
    float bm = red[0];
    #pragma unroll
    for (int w = 1; w < 8; w++) bm = fmaxf(bm, red[w]);

    float e = __expf(sim - bm);
    #pragma unroll
    for (int o = 16; o > 0; o >>= 1) e += __shfl_xor_sync(0xffffffffu, e, o);
    __syncthreads();               // WAR on red
    if (tx == 0) red[ty] = e;
    __syncthreads();
    if (tid == 0) {
        float s = 0.f;
        #pragma unroll
        for (int w = 0; w < 8; w++) s += red[w];
        float lse = bm + logf(s);
        g_rowloss[i] = lse - s_lab;
    }
}

// =======================================================================
// Kernel 5: final reduction. 1 block, 256 threads.
// =======================================================================
__global__ void k_final(float* __restrict__ out) {
    int tid = threadIdx.x;
    __shared__ float red[8];

    float c = g_rowloss[tid] * (1.f / 256.f);    // ntxent contribution
    if (tid < NG) {                               // topo contribution
        float t = 0.f;
        #pragma unroll
        for (int k = 0; k < KB; k++) {
            float d = g_sig[tid * KB + k] - g_sig[(NG + tid) * KB + k];
            t += d * d;
        }
        c += t * (1.f / (float)(KB * NG));
    }

    int ty = tid >> 5, tx = tid & 31;
    #pragma unroll
    for (int o = 16; o > 0; o >>= 1) c += __shfl_down_sync(0xffffffffu, c, o);
    if (tx == 0) red[ty] = c;
    __syncthreads();
    if (tid == 0) {
        float s = 0.f;
        #pragma unroll
        for (int w = 0; w < 8; w++) s += red[w];
        out[0] = 0.1f * s;    // LAMBDA
    }
}

// =======================================================================
extern "C" void kernel_launch(void* const* d_in, const int* in_sizes, int n_in,
                              void* d_out, int out_size) {
    const float* H1 = (const float*)d_in[0];
    const float* H2 = (const float*)d_in[2];
    const float* z1 = (const float*)d_in[4];
    const float* z2 = (const float*)d_in[5];
    float* out = (float*)d_out;

    k_sq<<<257, 256>>>(H1, H2, z1, z2);
    k_gram<<<768, 256>>>(H1, H2);
    k_hist<<<1024, 256>>>();
    k_sig<<<16, 256>>>();
    k_ntx<<<256, 256>>>(z1, z2);
    k_final<<<1, 256>>>(out);
}